// round 2
// baseline (speedup 1.0000x reference)
#include <cuda_runtime.h>
#include <math.h>

#define N_TOK 8192
#define DIM   4096
#define NEXP  16
#define TPB   256
#define NWARP 8
#define TOK_PER_BLK 64
#define KSLICE (DIM / NWARP)   /* 512 per warp */
#define GCHUNK 128             /* gate k-chunk staged in smem per warp */
#define XTILE  32              /* x k-tile staged in smem per warp */
#define XS_STRIDE 66           /* 64 tokens + pad (even, 8B-aligned rows) */

#define SMEM_GS   (NWARP * GCHUNK * NEXP)          /* 16384 f */
#define SMEM_XS   (NWARP * XTILE * XS_STRIDE)      /* 16896 f */
#define SMEM_PART (NWARP * TOK_PER_BLK * NEXP)     /*  8192 f */
#define SMEM_LG   (TOK_PER_BLK * NEXP)             /*  1024 f */
#define SMEM_FLOATS (SMEM_GS + SMEM_XS + SMEM_PART + SMEM_LG)
#define SMEM_BYTES (SMEM_FLOATS * 4)               /* 169984 B */

__global__ void __launch_bounds__(TPB, 1)
router_kernel(const float* __restrict__ x,
              const float* __restrict__ gate,
              float* __restrict__ out,
              int out_size)
{
    extern __shared__ float smem[];
    float* gs   = smem;                 // [NWARP][GCHUNK][16]
    float* xs   = gs + SMEM_GS;         // [NWARP][XTILE][XS_STRIDE] (k-major, transposed)
    float* part = xs + SMEM_XS;         // [NWARP][64][16]
    float* lg   = part + SMEM_PART;     // [64][16]

    const int tid = threadIdx.x;
    const int w   = tid >> 5;
    const int l   = tid & 31;
    const int tokBase = blockIdx.x * TOK_PER_BLK;

    float* gs_w = gs + w * (GCHUNK * NEXP);
    float* xs_w = xs + w * (XTILE * XS_STRIDE);
    const int kw = w * KSLICE;

    // 16 f32x2 accumulators: [token in {2l, 2l+1}] x [8 expert pairs]
    unsigned long long acc0[8], acc1[8];
#pragma unroll
    for (int i = 0; i < 8; i++) { acc0[i] = 0ull; acc1[i] = 0ull; }

    for (int kc = 0; kc < KSLICE; kc += GCHUNK) {
        // ---- stage gate chunk [GCHUNK][16] (contiguous, coalesced, L2-resident) ----
        __syncwarp();
        const float* gsrc = gate + (size_t)(kw + kc) * NEXP;
#pragma unroll
        for (int i = 0; i < (GCHUNK * NEXP) / (32 * 4); i++) {   // 16 iters
            int idx = (i * 32 + l) * 4;
            *(float4*)(gs_w + idx) = *(const float4*)(gsrc + idx);
        }
        __syncwarp();

        for (int kt = 0; kt < GCHUNK; kt += XTILE) {
            const int kpos = kw + kc + kt;
            __syncwarp();   // previous tile's reads complete before overwrite
            // ---- stage x tile: 64 tokens x 32 k, 128B row segments (nL=4/LDG),
            //      store transposed so compute lanes read consecutive tokens ----
#pragma unroll
            for (int i = 0; i < 16; i++) {
                int r = i * 4 + (l >> 3);        // token row 0..63
                int c = (l & 7) * 4;             // k col 0..28
                float4 v = *(const float4*)(x + (size_t)(tokBase + r) * DIM + kpos + c);
                xs_w[(c + 0) * XS_STRIDE + r] = v.x;
                xs_w[(c + 1) * XS_STRIDE + r] = v.y;
                xs_w[(c + 2) * XS_STRIDE + r] = v.z;
                xs_w[(c + 3) * XS_STRIDE + r] = v.w;
            }
            __syncwarp();

            // ---- compute: all lanes on same kk -> gate LDS is broadcast ----
            // NOTE: gate row within the staged chunk is (kt + kk)  [R1 bugfix]
#pragma unroll 8
            for (int kk = 0; kk < XTILE; kk++) {
                float2 xv = *(const float2*)(xs_w + kk * XS_STRIDE + 2 * l);
                unsigned long long xp0, xp1;
                asm("mov.b64 %0, {%1,%1};" : "=l"(xp0) : "f"(xv.x));
                asm("mov.b64 %0, {%1,%1};" : "=l"(xp1) : "f"(xv.y));
                const unsigned long long* grow =
                    (const unsigned long long*)(gs_w + (kt + kk) * NEXP);
#pragma unroll
                for (int ep = 0; ep < 8; ep++) {
                    unsigned long long g = grow[ep];
                    asm("fma.rn.f32x2 %0, %1, %2, %0;"
                        : "+l"(acc0[ep]) : "l"(xp0), "l"(g));
                    asm("fma.rn.f32x2 %0, %1, %2, %0;"
                        : "+l"(acc1[ep]) : "l"(xp1), "l"(g));
                }
            }
        }
    }

    // ---- write per-warp partials ----
    {
        unsigned long long* p0 =
            (unsigned long long*)(part + (size_t)(w * TOK_PER_BLK + 2 * l) * NEXP);
        unsigned long long* p1 =
            (unsigned long long*)(part + (size_t)(w * TOK_PER_BLK + 2 * l + 1) * NEXP);
#pragma unroll
        for (int ep = 0; ep < 8; ep++) { p0[ep] = acc0[ep]; p1[ep] = acc1[ep]; }
    }
    __syncthreads();

    // ---- reduce across 8 warps: thread handles (token, 4 experts) ----
    {
        int tok = tid >> 2, eg = tid & 3;
        float4 s = make_float4(0.f, 0.f, 0.f, 0.f);
#pragma unroll
        for (int ww = 0; ww < NWARP; ww++) {
            float4 v = *(float4*)(part + (size_t)(ww * TOK_PER_BLK + tok) * NEXP + eg * 4);
            s.x += v.x; s.y += v.y; s.z += v.z; s.w += v.w;
        }
        *(float4*)(lg + tok * NEXP + eg * 4) = s;
    }
    __syncthreads();

    // ---- top-2 + sigmoid + transposed score writes ----
    if (tid < TOK_PER_BLK) {
        int tok = tid;
        float v[NEXP];
#pragma unroll
        for (int e = 0; e < NEXP; e++) v[e] = lg[tok * NEXP + e];
        float v1 = -INFINITY, v2 = -INFINITY;
        int   i1 = -1,        i2 = -1;
#pragma unroll
        for (int e = 0; e < NEXP; e++) {
            float t = v[e];
            if (t > v1)      { v2 = v1; i2 = i1; v1 = t; i1 = e; }
            else if (t > v2) { v2 = t;  i2 = e; }
        }
        int gtok = tokBase + tok;
#pragma unroll
        for (int e = 0; e < NEXP; e++) {
            float sc = (e == i1 || e == i2) ? (1.0f / (1.0f + expf(-v[e]))) : 0.0f;
            out[(size_t)e * N_TOK + gtok] = sc;   // lanes -> consecutive tokens: coalesced
        }
    }

    // ---- token_indices (second output), written as float values ----
    if (out_size >= 2 * NEXP * N_TOK) {
        int c  = tid & 63;
        int e0 = tid >> 6;                  // 0..3
        int gtok = tokBase + c;
        float fv = (float)gtok;
#pragma unroll
        for (int r = 0; r < 4; r++) {
            int e = e0 * 4 + r;
            out[(size_t)NEXP * N_TOK + (size_t)e * N_TOK + gtok] = fv;
        }
    }
}

extern "C" void kernel_launch(void* const* d_in, const int* in_sizes, int n_in,
                              void* d_out, int out_size)
{
    const float* x    = (const float*)d_in[0];
    const float* gate = (const float*)d_in[1];
    float* out = (float*)d_out;

    cudaFuncSetAttribute(router_kernel,
                         cudaFuncAttributeMaxDynamicSharedMemorySize, SMEM_BYTES);

    dim3 grid(N_TOK / TOK_PER_BLK);   // 128 blocks
    dim3 block(TPB);
    router_kernel<<<grid, block, SMEM_BYTES>>>(x, gate, out, out_size);
}